// round 1
// baseline (speedup 1.0000x reference)
#include <cuda_runtime.h>
#include <cuda_bf16.h>
#include <cstdint>
#include <cstddef>

// Problem constants
#define BTOT   4096
#define NTOK   49
#define CDIM   384
#define HEADS  12
#define HDIM   32
#define MROWS  (BTOT * NTOK)        // 200704
#define KDIM   384
#define N_QKV  1152

// Scratch (alloc-free rule: __device__ globals)
__device__ float g_qkv[(size_t)MROWS * N_QKV];   // ~925 MB
__device__ float g_ctx[(size_t)MROWS * CDIM];    // ~308 MB

// ---------------------------------------------------------------------------
// tf32 helpers
// ---------------------------------------------------------------------------
__device__ __forceinline__ float tf32r(float x) {
    uint32_t u;
    asm("cvt.rna.tf32.f32 %0, %1;" : "=r"(u) : "f"(x));
    return __uint_as_float(u);
}
__device__ __forceinline__ uint32_t fau(float x) { return __float_as_uint(x); }

__device__ __forceinline__ void mma_tf32(float c[4], const uint32_t a[4], const uint32_t b[2]) {
    asm volatile(
        "mma.sync.aligned.m16n8k8.row.col.f32.tf32.tf32.f32 "
        "{%0,%1,%2,%3}, {%4,%5,%6,%7}, {%8,%9}, {%0,%1,%2,%3};"
        : "+f"(c[0]), "+f"(c[1]), "+f"(c[2]), "+f"(c[3])
        : "r"(a[0]), "r"(a[1]), "r"(a[2]), "r"(a[3]), "r"(b[0]), "r"(b[1]));
}

// ---------------------------------------------------------------------------
// GEMM: C[M x Ncols] = A[M x 384] * B[384 x Ncols] + bias
// Block tile 128x64, BK=32, 256 threads (8 warps, 4x2), warp tile 32x32.
// Double-buffered smem, tf32 mma.sync.
// ---------------------------------------------------------------------------
#define AS_STRIDE 132   // 128 + 4 pad (conflict-free frag loads)
#define BS_STRIDE 72    // 64 + 8 pad  (conflict-free frag loads)
#define AS_TILE   (32 * AS_STRIDE)
#define BS_TILE   (32 * BS_STRIDE)
#define KT_ITERS  12    // 384 / 32

__global__ void __launch_bounds__(256, 2)
gemm_tf32_kernel(const float* __restrict__ A, const float* __restrict__ B,
                 const float* __restrict__ bias, float* __restrict__ C, int Ncols)
{
    extern __shared__ float smem[];
    float* As = smem;                 // [2][32][AS_STRIDE], stored transposed: As[k][m]
    float* Bs = smem + 2 * AS_TILE;   // [2][32][BS_STRIDE]: Bs[k][n]

    const int tid  = threadIdx.x;
    const int warp = tid >> 5, lane = tid & 31;
    const int wm   = warp >> 1, wn = warp & 1;
    const int g    = lane >> 2, t = lane & 3;
    const int m0   = blockIdx.y * 128;
    const int n0   = blockIdx.x * 64;

    float acc[2][4][4];
    #pragma unroll
    for (int mi = 0; mi < 2; mi++)
        #pragma unroll
        for (int nj = 0; nj < 4; nj++)
            #pragma unroll
            for (int r = 0; r < 4; r++) acc[mi][nj][r] = 0.f;

    // loader index precompute
    const int aM  = tid >> 3;          // base m for i=0 (idx = tid + i*256; m = idx>>3)
    const int aK4 = tid & 7;
    const int bK  = tid >> 4;
    const int bN4 = tid & 15;

    float4 aR[4], bR[2];

    auto load_regs = [&](int kt) {
        const int k0 = kt * 32;
        #pragma unroll
        for (int i = 0; i < 4; i++) {
            int m = aM + i * 32;       // (tid + i*256) >> 3
            aR[i] = *(const float4*)(A + (size_t)(m0 + m) * KDIM + k0 + aK4 * 4);
        }
        #pragma unroll
        for (int i = 0; i < 2; i++) {
            int k = bK + i * 16;       // (tid + i*256) >> 4
            bR[i] = *(const float4*)(B + (size_t)(k0 + k) * Ncols + n0 + bN4 * 4);
        }
    };

    auto store_regs = [&](int s) {
        float* as = As + s * AS_TILE;
        #pragma unroll
        for (int i = 0; i < 4; i++) {
            int m = aM + i * 32;
            as[(aK4 * 4 + 0) * AS_STRIDE + m] = tf32r(aR[i].x);
            as[(aK4 * 4 + 1) * AS_STRIDE + m] = tf32r(aR[i].y);
            as[(aK4 * 4 + 2) * AS_STRIDE + m] = tf32r(aR[i].z);
            as[(aK4 * 4 + 3) * AS_STRIDE + m] = tf32r(aR[i].w);
        }
        float* bs = Bs + s * BS_TILE;
        #pragma unroll
        for (int i = 0; i < 2; i++) {
            int k = bK + i * 16;
            float4 v = bR[i];
            v.x = tf32r(v.x); v.y = tf32r(v.y); v.z = tf32r(v.z); v.w = tf32r(v.w);
            *(float4*)(bs + k * BS_STRIDE + bN4 * 4) = v;
        }
    };

    auto compute = [&](int s) {
        const float* as = As + s * AS_TILE;
        const float* bs = Bs + s * BS_TILE;
        #pragma unroll
        for (int kk = 0; kk < 4; kk++) {
            uint32_t afr[2][4], bfr[4][2];
            #pragma unroll
            for (int mi = 0; mi < 2; mi++) {
                int mb = wm * 32 + mi * 16;
                afr[mi][0] = fau(as[(kk * 8 + t) * AS_STRIDE + mb + g]);
                afr[mi][1] = fau(as[(kk * 8 + t) * AS_STRIDE + mb + g + 8]);
                afr[mi][2] = fau(as[(kk * 8 + t + 4) * AS_STRIDE + mb + g]);
                afr[mi][3] = fau(as[(kk * 8 + t + 4) * AS_STRIDE + mb + g + 8]);
            }
            #pragma unroll
            for (int nj = 0; nj < 4; nj++) {
                int nb = wn * 32 + nj * 8;
                bfr[nj][0] = fau(bs[(kk * 8 + t) * BS_STRIDE + nb + g]);
                bfr[nj][1] = fau(bs[(kk * 8 + t + 4) * BS_STRIDE + nb + g]);
            }
            #pragma unroll
            for (int mi = 0; mi < 2; mi++)
                #pragma unroll
                for (int nj = 0; nj < 4; nj++)
                    mma_tf32(acc[mi][nj], afr[mi], bfr[nj]);
        }
    };

    // prologue
    load_regs(0);
    store_regs(0);
    __syncthreads();

    int s = 0;
    #pragma unroll 1
    for (int kt = 0; kt < KT_ITERS; kt++) {
        if (kt + 1 < KT_ITERS) load_regs(kt + 1);
        compute(s);
        if (kt + 1 < KT_ITERS) store_regs(s ^ 1);
        __syncthreads();
        s ^= 1;
    }

    // epilogue: bias + store
    #pragma unroll
    for (int mi = 0; mi < 2; mi++) {
        #pragma unroll
        for (int nj = 0; nj < 4; nj++) {
            int row = m0 + wm * 32 + mi * 16 + g;
            int col = n0 + wn * 32 + nj * 8 + 2 * t;
            float b0 = bias[col], b1 = bias[col + 1];
            C[(size_t)row * Ncols + col]           = acc[mi][nj][0] + b0;
            C[(size_t)row * Ncols + col + 1]       = acc[mi][nj][1] + b1;
            C[(size_t)(row + 8) * Ncols + col]     = acc[mi][nj][2] + b0;
            C[(size_t)(row + 8) * Ncols + col + 1] = acc[mi][nj][3] + b1;
        }
    }
}

// ---------------------------------------------------------------------------
// Attention: one block per (window, head). 128 threads.
// smem q/k/v padded to stride 33 to avoid 32-way bank conflicts.
// ---------------------------------------------------------------------------
__global__ void __launch_bounds__(128)
attn_kernel(const float* __restrict__ qkv, const int* __restrict__ rel_index,
            const float* __restrict__ table, float* __restrict__ ctx)
{
    __shared__ float q[NTOK * 33];
    __shared__ float k[NTOK * 33];
    __shared__ float v[NTOK * 33];
    __shared__ float s[NTOK * NTOK];

    const int w = blockIdx.x, h = blockIdx.y;
    const int tid = threadIdx.x;
    const float scale = 0.1767766952966369f;   // 32^-0.5

    const size_t base = (size_t)w * NTOK * N_QKV + (size_t)h * HDIM;
    for (int idx = tid; idx < NTOK * HDIM; idx += 128) {
        int i = idx >> 5, d = idx & 31;
        size_t r = base + (size_t)i * N_QKV + d;
        q[i * 33 + d] = qkv[r] * scale;
        k[i * 33 + d] = qkv[r + CDIM];
        v[i * 33 + d] = qkv[r + 2 * CDIM];
    }
    __syncthreads();

    // scores + relative position bias
    for (int idx = tid; idx < NTOK * NTOK; idx += 128) {
        int i = idx / NTOK, j = idx - i * NTOK;
        float dot = 0.f;
        #pragma unroll 8
        for (int d = 0; d < HDIM; d++) dot += q[i * 33 + d] * k[j * 33 + d];
        s[idx] = dot + table[rel_index[idx] * HEADS + h];
    }
    __syncthreads();

    // softmax over rows (warp per row)
    const int wid = tid >> 5, lane = tid & 31;
    for (int r = wid; r < NTOK; r += 4) {
        float v0 = s[r * NTOK + lane];
        float v1 = (lane + 32 < NTOK) ? s[r * NTOK + lane + 32] : -1e30f;
        float m = fmaxf(v0, v1);
        #pragma unroll
        for (int o = 16; o; o >>= 1) m = fmaxf(m, __shfl_xor_sync(0xffffffffu, m, o));
        float e0 = __expf(v0 - m);
        float e1 = (lane + 32 < NTOK) ? __expf(v1 - m) : 0.f;
        float sum = e0 + e1;
        #pragma unroll
        for (int o = 16; o; o >>= 1) sum += __shfl_xor_sync(0xffffffffu, sum, o);
        float inv = 1.f / sum;
        s[r * NTOK + lane] = e0 * inv;
        if (lane + 32 < NTOK) s[r * NTOK + lane + 32] = e1 * inv;
    }
    __syncthreads();

    // out = attn @ v  -> ctx laid out (B*N, C) with col = h*32+d
    for (int idx = tid; idx < NTOK * HDIM; idx += 128) {
        int i = idx >> 5, d = idx & 31;
        float acc = 0.f;
        #pragma unroll 7
        for (int j = 0; j < NTOK; j++) acc += s[i * NTOK + j] * v[j * 33 + d];
        ctx[((size_t)w * NTOK + i) * CDIM + h * HDIM + d] = acc;
    }
}

// ---------------------------------------------------------------------------
// Launch
// ---------------------------------------------------------------------------
extern "C" void kernel_launch(void* const* d_in, const int* in_sizes, int n_in,
                              void* d_out, int out_size)
{
    const float* x     = (const float*)d_in[0];
    const float* Wqkv  = (const float*)d_in[1];
    const float* bqkv  = (const float*)d_in[2];
    const float* Wproj = (const float*)d_in[3];
    const float* bproj = (const float*)d_in[4];
    const float* table = (const float*)d_in[5];
    const int*   relix = (const int*)d_in[6];
    float* out = (float*)d_out;

    float* qkv = nullptr;
    float* ctx = nullptr;
    cudaGetSymbolAddress((void**)&qkv, g_qkv);
    cudaGetSymbolAddress((void**)&ctx, g_ctx);

    const int smem_bytes = (2 * AS_TILE + 2 * BS_TILE) * (int)sizeof(float);  // 52224
    cudaFuncSetAttribute(gemm_tf32_kernel,
                         cudaFuncAttributeMaxDynamicSharedMemorySize, smem_bytes);

    // 1) qkv = x @ W_qkv + b_qkv     (M=200704, N=1152, K=384)
    gemm_tf32_kernel<<<dim3(N_QKV / 64, MROWS / 128), 256, smem_bytes>>>(
        x, Wqkv, bqkv, qkv, N_QKV);

    // 2) attention per (window, head)
    attn_kernel<<<dim3(BTOT, HEADS), 128>>>(qkv, relix, table, ctx);

    // 3) out = ctx @ W_proj + b_proj (M=200704, N=384, K=384)
    gemm_tf32_kernel<<<dim3(CDIM / 64, MROWS / 128), 256, smem_bytes>>>(
        ctx, Wproj, bproj, out, CDIM);
}

// round 3
// speedup vs baseline: 1.8590x; 1.8590x over previous
#include <cuda_runtime.h>
#include <cuda_bf16.h>
#include <cstdint>
#include <cstddef>

// ---------------------------------------------------------------------------
// Problem constants
// ---------------------------------------------------------------------------
#define BTOT   4096
#define NTOK   49
#define CDIM   384
#define HEADS  12
#define HDIM   32
#define MROWS  (BTOT * NTOK)        // 200704
#define KDIM   384
#define N_QKV  1152

// Scratch (__device__ globals: the allowed alloc-free pattern)
__device__ float g_qkv[(size_t)MROWS * N_QKV];   // ~925 MB
__device__ float g_ctx[(size_t)MROWS * CDIM];    // ~308 MB (tf32-rounded by attn)
__device__ float g_xr [(size_t)MROWS * KDIM];    // ~308 MB (tf32-rounded x)
__device__ float g_wq [(size_t)KDIM * N_QKV];    // W_qkv rounded (row-major K x N)
__device__ float g_wp [(size_t)KDIM * CDIM];     // W_proj rounded

// ---------------------------------------------------------------------------
// Helpers
// ---------------------------------------------------------------------------
__device__ __forceinline__ float tf32r(float x) {
    uint32_t u;
    asm("cvt.rna.tf32.f32 %0, %1;" : "=r"(u) : "f"(x));
    return __uint_as_float(u);
}
__device__ __forceinline__ uint32_t fau(float x) { return __float_as_uint(x); }

__device__ __forceinline__ uint32_t smem_u32(const void* p) {
    return (uint32_t)__cvta_generic_to_shared(p);
}
__device__ __forceinline__ void cp16(uint32_t dst, const void* src) {
    asm volatile("cp.async.cg.shared.global [%0], [%1], 16;" :: "r"(dst), "l"(src));
}
__device__ __forceinline__ void cp_commit() {
    asm volatile("cp.async.commit_group;" ::: "memory");
}
__device__ __forceinline__ void cp_wait2() {
    asm volatile("cp.async.wait_group 2;" ::: "memory");
}

__device__ __forceinline__ void mma_tf32(float c[4], const uint32_t a[4], const uint32_t b[2]) {
    asm volatile(
        "mma.sync.aligned.m16n8k8.row.col.f32.tf32.tf32.f32 "
        "{%0,%1,%2,%3}, {%4,%5,%6,%7}, {%8,%9}, {%0,%1,%2,%3};"
        : "+f"(c[0]), "+f"(c[1]), "+f"(c[2]), "+f"(c[3])
        : "r"(a[0]), "r"(a[1]), "r"(a[2]), "r"(a[3]), "r"(b[0]), "r"(b[1]));
}

// ---------------------------------------------------------------------------
// Prep: elementwise tf32 rounding (x, W_qkv, W_proj)
// ---------------------------------------------------------------------------
__global__ void round_tf32_kernel(const float4* __restrict__ in,
                                  float4* __restrict__ out, int n4)
{
    for (int i = blockIdx.x * blockDim.x + threadIdx.x; i < n4;
         i += gridDim.x * blockDim.x) {
        float4 v = in[i];
        v.x = tf32r(v.x); v.y = tf32r(v.y); v.z = tf32r(v.z); v.w = tf32r(v.w);
        out[i] = v;
    }
}

// ---------------------------------------------------------------------------
// GEMM: C[M x Ncols] = A[M x 384] @ B[384 x Ncols] + bias   (A, B tf32-rounded)
// CTA 128x128, 128 threads = 4 warps (2x2), warp tile 64x64.
// BK=32, 3-stage cp.async pipeline, tf32 mma.sync m16n8k8.
//
// Smem layouts (per stage):
//   As[m][k]: 128 rows x 36 floats (32 data + 4 pad)  -> frag banks: 4g+t, CF
//   Bs[k][n]: 32 rows x 132 floats (128 data + 4 pad) -> frag banks: 4t+g, CF
// ---------------------------------------------------------------------------
#define AS_STRIDE 36
#define BS_STRIDE 132
#define AS_BYTES  (128 * AS_STRIDE * 4)   // 18432
#define BS_BYTES  (32 * BS_STRIDE * 4)    // 16896
#define STG_BYTES (AS_BYTES + BS_BYTES)   // 35328
#define GEMM_SMEM (3 * STG_BYTES)         // 105984

__global__ void __launch_bounds__(128)
gemm_tf32_kernel(const float* __restrict__ A, const float* __restrict__ B,
                 const float* __restrict__ bias, float* __restrict__ C, int Ncols)
{
    extern __shared__ char smem[];
    const uint32_t sb = smem_u32(smem);

    const int tid  = threadIdx.x;
    const int warp = tid >> 5, lane = tid & 31;
    const int wm   = warp >> 1, wn = warp & 1;
    const int g    = lane >> 2, t = lane & 3;
    const int m0   = blockIdx.y * 128;
    const int n0   = blockIdx.x * 128;

    float acc[4][8][4];
    #pragma unroll
    for (int mi = 0; mi < 4; mi++)
        #pragma unroll
        for (int nj = 0; nj < 8; nj++)
            #pragma unroll
            for (int r = 0; r < 4; r++) acc[mi][nj][r] = 0.f;

    const char* gA = (const char*)(A + (size_t)m0 * KDIM);
    const char* gB = (const char*)B;

    // stage loader: 8 A-chunks + 8 B-chunks of 16B per thread
    auto load_stage = [&](int kt, int s) {
        const uint32_t sA = sb + s * STG_BYTES;
        const uint32_t sB = sA + AS_BYTES;
        const size_t kbA = (size_t)kt * 128;          // byte offset along K in A row
        #pragma unroll
        for (int j = 0; j < 8; j++) {
            int c = tid + j * 128;                    // 0..1023
            int row = c >> 3, cic = c & 7;            // A: 128 rows x 8 chunks
            cp16(sA + row * (AS_STRIDE * 4) + cic * 16,
                 gA + (size_t)row * (KDIM * 4) + kbA + cic * 16);
        }
        #pragma unroll
        for (int j = 0; j < 8; j++) {
            int c = tid + j * 128;
            int row = c >> 5, cic = c & 31;           // B: 32 rows x 32 chunks
            cp16(sB + row * (BS_STRIDE * 4) + cic * 16,
                 gB + (size_t)(kt * 32 + row) * ((size_t)Ncols * 4)
                    + (size_t)n0 * 4 + cic * 16);
        }
    };

    auto compute = [&](int s) {
        const float* as = (const float*)(smem + s * STG_BYTES);
        const float* bs = (const float*)(smem + s * STG_BYTES + AS_BYTES);
        #pragma unroll
        for (int kk = 0; kk < 4; kk++) {
            uint32_t afr[4][4], bfr[8][2];
            #pragma unroll
            for (int mi = 0; mi < 4; mi++) {
                int mb = wm * 64 + mi * 16;
                afr[mi][0] = fau(as[(mb + g)     * AS_STRIDE + kk * 8 + t]);
                afr[mi][1] = fau(as[(mb + g + 8) * AS_STRIDE + kk * 8 + t]);
                afr[mi][2] = fau(as[(mb + g)     * AS_STRIDE + kk * 8 + t + 4]);
                afr[mi][3] = fau(as[(mb + g + 8) * AS_STRIDE + kk * 8 + t + 4]);
            }
            #pragma unroll
            for (int nj = 0; nj < 8; nj++) {
                int nb = wn * 64 + nj * 8;
                bfr[nj][0] = fau(bs[(kk * 8 + t)     * BS_STRIDE + nb + g]);
                bfr[nj][1] = fau(bs[(kk * 8 + t + 4) * BS_STRIDE + nb + g]);
            }
            #pragma unroll
            for (int mi = 0; mi < 4; mi++)
                #pragma unroll
                for (int nj = 0; nj < 8; nj++)
                    mma_tf32(acc[mi][nj], afr[mi], bfr[nj]);
        }
    };

    load_stage(0, 0); cp_commit();
    load_stage(1, 1); cp_commit();
    load_stage(2, 2); cp_commit();

    #pragma unroll 1
    for (int kt = 0; kt < 12; kt++) {
        int s = kt % 3;
        cp_wait2();
        __syncthreads();
        compute(s);
        __syncthreads();
        if (kt + 3 < 12) load_stage(kt + 3, s);
        cp_commit();                     // one group per iter keeps count exact
    }

    // epilogue: direct float2 stores (32B-sector aligned per 4-lane group)
    #pragma unroll
    for (int mi = 0; mi < 4; mi++) {
        #pragma unroll
        for (int nj = 0; nj < 8; nj++) {
            int row = m0 + wm * 64 + mi * 16 + g;
            int col = n0 + wn * 64 + nj * 8 + 2 * t;
            float2 bb = *(const float2*)(bias + col);
            float2 v0 = make_float2(acc[mi][nj][0] + bb.x, acc[mi][nj][1] + bb.y);
            float2 v1 = make_float2(acc[mi][nj][2] + bb.x, acc[mi][nj][3] + bb.y);
            *(float2*)(C + (size_t)row * Ncols + col)       = v0;
            *(float2*)(C + (size_t)(row + 8) * Ncols + col) = v1;
        }
    }
}

// ---------------------------------------------------------------------------
// Attention: one block per (window, head). 192 threads, 4x4 register tiles.
// ---------------------------------------------------------------------------
#define ST 51
__global__ void __launch_bounds__(192)
attn_kernel(const float* __restrict__ qkv, const int* __restrict__ rel_index,
            const float* __restrict__ table, float* __restrict__ ctx)
{
    __shared__ float q[NTOK * 33];
    __shared__ float k[NTOK * 33];
    __shared__ float v[NTOK * 33];
    __shared__ float s[NTOK * ST];

    const int w = blockIdx.x, h = blockIdx.y;
    const int t = threadIdx.x;
    const float scale = 0.1767766952966369f;   // 32^-0.5

    const size_t base = (size_t)w * NTOK * N_QKV + (size_t)h * HDIM;
    for (int idx = t; idx < NTOK * HDIM; idx += 192) {
        int i = idx >> 5, d = idx & 31;
        size_t r = base + (size_t)i * N_QKV + d;
        q[i * 33 + d] = qkv[r] * scale;
        k[i * 33 + d] = qkv[r + CDIM];
        v[i * 33 + d] = qkv[r + 2 * CDIM];
    }
    __syncthreads();

    // S = (q*scale) K^T + bias, 4x4 register tiles over 169 threads
    if (t < 169) {
        const int ti = t / 13, tj = t % 13;
        const int i0 = ti * 4, j0 = tj * 4;
        float acc[4][4];
        #pragma unroll
        for (int r = 0; r < 4; r++)
            #pragma unroll
            for (int c = 0; c < 4; c++) {
                int i = i0 + r, j = j0 + c;
                acc[r][c] = (i < NTOK && j < NTOK)
                          ? table[rel_index[i * NTOK + j] * HEADS + h] : 0.f;
            }
        #pragma unroll 8
        for (int d = 0; d < HDIM; d++) {
            float qr[4], kc[4];
            #pragma unroll
            for (int r = 0; r < 4; r++) qr[r] = q[min(i0 + r, NTOK - 1) * 33 + d];
            #pragma unroll
            for (int c = 0; c < 4; c++) kc[c] = k[min(j0 + c, NTOK - 1) * 33 + d];
            #pragma unroll
            for (int r = 0; r < 4; r++)
                #pragma unroll
                for (int c = 0; c < 4; c++) acc[r][c] += qr[r] * kc[c];
        }
        #pragma unroll
        for (int r = 0; r < 4; r++)
            #pragma unroll
            for (int c = 0; c < 4; c++) {
                int i = i0 + r, j = j0 + c;
                if (i < NTOK && j < NTOK) s[i * ST + j] = acc[r][c];
            }
    }
    __syncthreads();

    // softmax over rows, one warp per row (6 warps)
    const int wid = t >> 5, lane = t & 31;
    for (int r = wid; r < NTOK; r += 6) {
        float v0 = s[r * ST + lane];
        float v1 = (lane + 32 < NTOK) ? s[r * ST + lane + 32] : -1e30f;
        float m = fmaxf(v0, v1);
        #pragma unroll
        for (int o = 16; o; o >>= 1) m = fmaxf(m, __shfl_xor_sync(0xffffffffu, m, o));
        float e0 = __expf(v0 - m);
        float e1 = (lane + 32 < NTOK) ? __expf(v1 - m) : 0.f;
        float sum = e0 + e1;
        #pragma unroll
        for (int o = 16; o; o >>= 1) sum += __shfl_xor_sync(0xffffffffu, sum, o);
        float inv = 1.f / sum;
        s[r * ST + lane] = e0 * inv;
        if (lane + 32 < NTOK) s[r * ST + lane + 32] = e1 * inv;
    }
    __syncthreads();

    // out = attn @ v, 4x4 register tiles (i x d) over 104 threads
    // ctx written tf32-rounded (it feeds the proj GEMM directly)
    if (t < 104) {
        const int it = t >> 3, dt = t & 7;
        const int i0 = it * 4, d0 = dt * 4;
        float acc[4][4] = {};
        #pragma unroll 7
        for (int j = 0; j < NTOK; j++) {
            float sv[4], vv[4];
            #pragma unroll
            for (int r = 0; r < 4; r++) sv[r] = s[min(i0 + r, NTOK - 1) * ST + j];
            #pragma unroll
            for (int c = 0; c < 4; c++) vv[c] = v[j * 33 + d0 + c];
            #pragma unroll
            for (int r = 0; r < 4; r++)
                #pragma unroll
                for (int c = 0; c < 4; c++) acc[r][c] += sv[r] * vv[c];
        }
        #pragma unroll
        for (int r = 0; r < 4; r++) {
            int i = i0 + r;
            if (i < NTOK) {
                #pragma unroll
                for (int c = 0; c < 4; c++)
                    ctx[((size_t)w * NTOK + i) * CDIM + h * HDIM + d0 + c] =
                        tf32r(acc[r][c]);
            }
        }
    }
}

// ---------------------------------------------------------------------------
// Launch
// ---------------------------------------------------------------------------
extern "C" void kernel_launch(void* const* d_in, const int* in_sizes, int n_in,
                              void* d_out, int out_size)
{
    const float* x     = (const float*)d_in[0];
    const float* Wqkv  = (const float*)d_in[1];
    const float* bqkv  = (const float*)d_in[2];
    const float* Wproj = (const float*)d_in[3];
    const float* bproj = (const float*)d_in[4];
    const float* table = (const float*)d_in[5];
    const int*   relix = (const int*)d_in[6];
    float* out = (float*)d_out;

    float *qkv, *ctx, *xr, *wq, *wp;
    cudaGetSymbolAddress((void**)&qkv, g_qkv);
    cudaGetSymbolAddress((void**)&ctx, g_ctx);
    cudaGetSymbolAddress((void**)&xr,  g_xr);
    cudaGetSymbolAddress((void**)&wq,  g_wq);
    cudaGetSymbolAddress((void**)&wp,  g_wp);

    cudaFuncSetAttribute(gemm_tf32_kernel,
                         cudaFuncAttributeMaxDynamicSharedMemorySize, GEMM_SMEM);

    // 0) prep: tf32-round x and weights (elementwise, layout unchanged)
    round_tf32_kernel<<<4096, 256>>>((const float4*)x, (float4*)xr,
                                     (MROWS * KDIM) / 4);
    round_tf32_kernel<<<432, 256>>>((const float4*)Wqkv, (float4*)wq,
                                    (KDIM * N_QKV) / 4);
    round_tf32_kernel<<<144, 256>>>((const float4*)Wproj, (float4*)wp,
                                    (KDIM * CDIM) / 4);

    // 1) qkv = x @ W_qkv + b     (M=200704, N=1152, K=384)
    gemm_tf32_kernel<<<dim3(N_QKV / 128, MROWS / 128), 128, GEMM_SMEM>>>(
        xr, wq, bqkv, qkv, N_QKV);

    // 2) attention per (window, head)
    attn_kernel<<<dim3(BTOT, HEADS), 192>>>(qkv, relix, table, ctx);

    // 3) out = ctx @ W_proj + b  (M=200704, N=384, K=384)
    gemm_tf32_kernel<<<dim3(CDIM / 128, MROWS / 128), 128, GEMM_SMEM>>>(
        ctx, wp, bproj, out, CDIM);
}

// round 5
// speedup vs baseline: 2.1054x; 1.1326x over previous
#include <cuda_runtime.h>
#include <cuda_bf16.h>
#include <cstdint>
#include <cstddef>

// ---------------------------------------------------------------------------
// Problem constants
// ---------------------------------------------------------------------------
#define BTOT   4096
#define NTOK   49
#define CDIM   384
#define HEADS  12
#define HDIM   32
#define MROWS  (BTOT * NTOK)        // 200704
#define KDIM   384
#define N_QKV  1152

// Scratch (__device__ globals: the allowed alloc-free pattern)
__device__ float g_qkv[(size_t)MROWS * N_QKV];   // ~925 MB
__device__ float g_ctx[(size_t)MROWS * CDIM];    // ~308 MB (tf32-rounded by attn)
__device__ float g_wq [(size_t)KDIM * N_QKV];    // W_qkv rounded (row-major K x N)
__device__ float g_wp [(size_t)KDIM * CDIM];     // W_proj rounded

// ---------------------------------------------------------------------------
// Helpers
// ---------------------------------------------------------------------------
__device__ __forceinline__ float tf32r(float x) {
    uint32_t u;
    asm("cvt.rna.tf32.f32 %0, %1;" : "=r"(u) : "f"(x));
    return __uint_as_float(u);
}
__device__ __forceinline__ uint32_t fautf(float x) {   // round + reinterpret
    uint32_t u;
    asm("cvt.rna.tf32.f32 %0, %1;" : "=r"(u) : "f"(x));
    return u;
}
__device__ __forceinline__ uint32_t fau(float x) { return __float_as_uint(x); }

__device__ __forceinline__ uint32_t smem_u32(const void* p) {
    return (uint32_t)__cvta_generic_to_shared(p);
}
__device__ __forceinline__ void cp16(uint32_t dst, const void* src) {
    asm volatile("cp.async.cg.shared.global [%0], [%1], 16;" :: "r"(dst), "l"(src));
}
__device__ __forceinline__ void cp_commit() {
    asm volatile("cp.async.commit_group;" ::: "memory");
}
__device__ __forceinline__ void cp_wait1() {
    asm volatile("cp.async.wait_group 1;" ::: "memory");
}

__device__ __forceinline__ void mma_tf32(float c[4], const uint32_t a[4], const uint32_t b[2]) {
    asm volatile(
        "mma.sync.aligned.m16n8k8.row.col.f32.tf32.tf32.f32 "
        "{%0,%1,%2,%3}, {%4,%5,%6,%7}, {%8,%9}, {%0,%1,%2,%3};"
        : "+f"(c[0]), "+f"(c[1]), "+f"(c[2]), "+f"(c[3])
        : "r"(a[0]), "r"(a[1]), "r"(a[2]), "r"(a[3]), "r"(b[0]), "r"(b[1]));
}

// ---------------------------------------------------------------------------
// Prep: elementwise tf32 rounding (weights only; A is rounded on the fly)
// ---------------------------------------------------------------------------
__global__ void round_tf32_kernel(const float4* __restrict__ in,
                                  float4* __restrict__ out, int n4)
{
    for (int i = blockIdx.x * blockDim.x + threadIdx.x; i < n4;
         i += gridDim.x * blockDim.x) {
        float4 v = in[i];
        v.x = tf32r(v.x); v.y = tf32r(v.y); v.z = tf32r(v.z); v.w = tf32r(v.w);
        out[i] = v;
    }
}

// ---------------------------------------------------------------------------
// GEMM: C[M x Ncols] = A[M x 384] @ B[384 x Ncols] + bias
// A: raw fp32 (tf32-rounded after LDS).  B: pre-rounded tf32.
// CTA 128x128, 128 threads = 4 warps (2x2), warp tile 64x64.
// BK=32, 2-stage cp.async pipeline (70.6 KB smem -> 3 CTAs/SM).
// ---------------------------------------------------------------------------
#define AS_STRIDE 36
#define BS_STRIDE 132
#define AS_BYTES  (128 * AS_STRIDE * 4)   // 18432
#define BS_BYTES  (32 * BS_STRIDE * 4)    // 16896
#define STG_BYTES (AS_BYTES + BS_BYTES)   // 35328
#define GEMM_SMEM (2 * STG_BYTES)         // 70656

__global__ void __launch_bounds__(128, 3)
gemm_tf32_kernel(const float* __restrict__ A, const float* __restrict__ B,
                 const float* __restrict__ bias, float* __restrict__ C, int Ncols)
{
    extern __shared__ char smem[];
    const uint32_t sb = smem_u32(smem);

    const int tid  = threadIdx.x;
    const int warp = tid >> 5, lane = tid & 31;
    const int wm   = warp >> 1, wn = warp & 1;
    const int g    = lane >> 2, t = lane & 3;
    const int m0   = blockIdx.y * 128;
    const int n0   = blockIdx.x * 128;

    float acc[4][8][4];
    #pragma unroll
    for (int mi = 0; mi < 4; mi++)
        #pragma unroll
        for (int nj = 0; nj < 8; nj++)
            #pragma unroll
            for (int r = 0; r < 4; r++) acc[mi][nj][r] = 0.f;

    const char* gA = (const char*)(A + (size_t)m0 * KDIM);
    const char* gB = (const char*)B;

    auto load_stage = [&](int kt, int s) {
        const uint32_t sA = sb + s * STG_BYTES;
        const uint32_t sB = sA + AS_BYTES;
        const size_t kbA = (size_t)kt * 128;          // byte offset along K
        #pragma unroll
        for (int j = 0; j < 8; j++) {
            int c = tid + j * 128;                    // 0..1023
            int row = c >> 3, cic = c & 7;            // A: 128 rows x 8 chunks
            cp16(sA + row * (AS_STRIDE * 4) + cic * 16,
                 gA + (size_t)row * (KDIM * 4) + kbA + cic * 16);
        }
        #pragma unroll
        for (int j = 0; j < 8; j++) {
            int c = tid + j * 128;
            int row = c >> 5, cic = c & 31;           // B: 32 rows x 32 chunks
            cp16(sB + row * (BS_STRIDE * 4) + cic * 16,
                 gB + (size_t)(kt * 32 + row) * ((size_t)Ncols * 4)
                    + (size_t)n0 * 4 + cic * 16);
        }
    };

    auto compute = [&](int s) {
        const float* as = (const float*)(smem + s * STG_BYTES);
        const float* bs = (const float*)(smem + s * STG_BYTES + AS_BYTES);
        #pragma unroll
        for (int kk = 0; kk < 4; kk++) {
            uint32_t afr[4][4], bfr[8][2];
            #pragma unroll
            for (int mi = 0; mi < 4; mi++) {
                int mb = wm * 64 + mi * 16;
                afr[mi][0] = fautf(as[(mb + g)     * AS_STRIDE + kk * 8 + t]);
                afr[mi][1] = fautf(as[(mb + g + 8) * AS_STRIDE + kk * 8 + t]);
                afr[mi][2] = fautf(as[(mb + g)     * AS_STRIDE + kk * 8 + t + 4]);
                afr[mi][3] = fautf(as[(mb + g + 8) * AS_STRIDE + kk * 8 + t + 4]);
            }
            #pragma unroll
            for (int nj = 0; nj < 8; nj++) {
                int nb = wn * 64 + nj * 8;
                bfr[nj][0] = fau(bs[(kk * 8 + t)     * BS_STRIDE + nb + g]);
                bfr[nj][1] = fau(bs[(kk * 8 + t + 4) * BS_STRIDE + nb + g]);
            }
            #pragma unroll
            for (int mi = 0; mi < 4; mi++)
                #pragma unroll
                for (int nj = 0; nj < 8; nj++)
                    mma_tf32(acc[mi][nj], afr[mi], bfr[nj]);
        }
    };

    load_stage(0, 0); cp_commit();
    load_stage(1, 1); cp_commit();

    #pragma unroll 1
    for (int kt = 0; kt < 12; kt++) {
        int s = kt & 1;
        cp_wait1();
        __syncthreads();
        compute(s);
        __syncthreads();
        if (kt + 2 < 12) load_stage(kt + 2, s);
        cp_commit();                     // one group per iter keeps count exact
    }

    // epilogue: direct float2 stores
    #pragma unroll
    for (int mi = 0; mi < 4; mi++) {
        #pragma unroll
        for (int nj = 0; nj < 8; nj++) {
            int row = m0 + wm * 64 + mi * 16 + g;
            int col = n0 + wn * 64 + nj * 8 + 2 * t;
            float2 bb = *(const float2*)(bias + col);
            float2 v0 = make_float2(acc[mi][nj][0] + bb.x, acc[mi][nj][1] + bb.y);
            float2 v1 = make_float2(acc[mi][nj][2] + bb.x, acc[mi][nj][3] + bb.y);
            *(float2*)(C + (size_t)row * Ncols + col)       = v0;
            *(float2*)(C + (size_t)(row + 8) * Ncols + col) = v1;
        }
    }
}

// ---------------------------------------------------------------------------
// Attention: one block per (window, head). 64 threads.
// S phase: 49 threads, exact 7x7 register tiles (no bounds checks).
// softmax: thread-per-row. O phase: 28 threads, 7x8 tiles, float4 V loads.
// NOTE: all shared arrays are __align__(16) — float4 LDS/STS require the
// array BASE to be 16B aligned (this was the round-4 misaligned-address bug).
// ---------------------------------------------------------------------------
#define QS 33
#define VS 36
#define ST 51
__global__ void __launch_bounds__(64)
attn_kernel(const float* __restrict__ qkv, const int* __restrict__ rel_index,
            const float* __restrict__ table, float* __restrict__ ctx)
{
    __shared__ __align__(16) float q[NTOK * QS];
    __shared__ __align__(16) float k[NTOK * QS];
    __shared__ __align__(16) float v[NTOK * VS];
    __shared__ __align__(16) float s[NTOK * ST];

    const int w = blockIdx.x, h = blockIdx.y;
    const int t = threadIdx.x;
    const float scale = 0.1767766952966369f;   // 32^-0.5

    // load q,k,v (float4 over d) + cooperative bias pre-fill into s
    for (int idx = t; idx < NTOK * 8; idx += 64) {
        int i = idx >> 3, d4 = (idx & 7) * 4;
        const float* row = qkv + ((size_t)w * NTOK + i) * N_QKV + h * HDIM + d4;
        float4 a = *(const float4*)(row);
        float4 b = *(const float4*)(row + CDIM);
        float4 c = *(const float4*)(row + 2 * CDIM);
        q[i * QS + d4 + 0] = a.x * scale; q[i * QS + d4 + 1] = a.y * scale;
        q[i * QS + d4 + 2] = a.z * scale; q[i * QS + d4 + 3] = a.w * scale;
        k[i * QS + d4 + 0] = b.x; k[i * QS + d4 + 1] = b.y;
        k[i * QS + d4 + 2] = b.z; k[i * QS + d4 + 3] = b.w;
        v[i * VS + d4 + 0] = c.x; v[i * VS + d4 + 1] = c.y;
        v[i * VS + d4 + 2] = c.z; v[i * VS + d4 + 3] = c.w;
    }
    for (int idx = t; idx < NTOK * NTOK; idx += 64) {
        int i = idx / NTOK, j = idx - i * NTOK;
        s[i * ST + j] = table[rel_index[idx] * HEADS + h];
    }
    __syncthreads();

    // S = q*scale @ K^T + bias : 49 threads, 7x7 tiles (exact cover)
    if (t < 49) {
        const int i0 = (t / 7) * 7, j0 = (t % 7) * 7;
        float acc[7][7];
        #pragma unroll
        for (int r = 0; r < 7; r++)
            #pragma unroll
            for (int c = 0; c < 7; c++)
                acc[r][c] = s[(i0 + r) * ST + j0 + c];
        #pragma unroll 4
        for (int d = 0; d < HDIM; d++) {
            float qr[7], kc[7];
            #pragma unroll
            for (int r = 0; r < 7; r++) qr[r] = q[(i0 + r) * QS + d];
            #pragma unroll
            for (int c = 0; c < 7; c++) kc[c] = k[(j0 + c) * QS + d];
            #pragma unroll
            for (int r = 0; r < 7; r++)
                #pragma unroll
                for (int c = 0; c < 7; c++) acc[r][c] += qr[r] * kc[c];
        }
        #pragma unroll
        for (int r = 0; r < 7; r++)
            #pragma unroll
            for (int c = 0; c < 7; c++)
                s[(i0 + r) * ST + j0 + c] = acc[r][c];
    }
    __syncthreads();

    // softmax: one thread per row
    if (t < NTOK) {
        float* row = s + t * ST;
        float m = row[0];
        #pragma unroll 7
        for (int j = 1; j < NTOK; j++) m = fmaxf(m, row[j]);
        float sum = 0.f;
        #pragma unroll 7
        for (int j = 0; j < NTOK; j++) { float e = __expf(row[j] - m); row[j] = e; sum += e; }
        float inv = 1.f / sum;
        #pragma unroll 7
        for (int j = 0; j < NTOK; j++) row[j] *= inv;
    }
    __syncthreads();

    // O = P @ V : 28 threads, 7 rows x 8 cols each
    if (t < 28) {
        const int i0 = (t >> 2) * 7, d0 = (t & 3) * 8;
        float acc[7][8] = {};
        #pragma unroll 7
        for (int j = 0; j < NTOK; j++) {
            float4 va = *(const float4*)(v + j * VS + d0);
            float4 vb = *(const float4*)(v + j * VS + d0 + 4);
            float vv[8] = {va.x, va.y, va.z, va.w, vb.x, vb.y, vb.z, vb.w};
            #pragma unroll
            for (int r = 0; r < 7; r++) {
                float sv = s[(i0 + r) * ST + j];
                #pragma unroll
                for (int c = 0; c < 8; c++) acc[r][c] += sv * vv[c];
            }
        }
        #pragma unroll
        for (int r = 0; r < 7; r++) {
            float* dst = ctx + ((size_t)w * NTOK + i0 + r) * CDIM + h * HDIM + d0;
            #pragma unroll
            for (int c = 0; c < 8; c++) dst[c] = tf32r(acc[r][c]);
        }
    }
}

// ---------------------------------------------------------------------------
// Launch
// ---------------------------------------------------------------------------
extern "C" void kernel_launch(void* const* d_in, const int* in_sizes, int n_in,
                              void* d_out, int out_size)
{
    const float* x     = (const float*)d_in[0];
    const float* Wqkv  = (const float*)d_in[1];
    const float* bqkv  = (const float*)d_in[2];
    const float* Wproj = (const float*)d_in[3];
    const float* bproj = (const float*)d_in[4];
    const float* table = (const float*)d_in[5];
    const int*   relix = (const int*)d_in[6];
    float* out = (float*)d_out;

    float *qkv, *ctx, *wq, *wp;
    cudaGetSymbolAddress((void**)&qkv, g_qkv);
    cudaGetSymbolAddress((void**)&ctx, g_ctx);
    cudaGetSymbolAddress((void**)&wq,  g_wq);
    cudaGetSymbolAddress((void**)&wp,  g_wp);

    cudaFuncSetAttribute(gemm_tf32_kernel,
                         cudaFuncAttributeMaxDynamicSharedMemorySize, GEMM_SMEM);

    // 0) prep: tf32-round weights only (x is rounded on the fly in the GEMM)
    round_tf32_kernel<<<432, 256>>>((const float4*)Wqkv, (float4*)wq,
                                    (KDIM * N_QKV) / 4);
    round_tf32_kernel<<<144, 256>>>((const float4*)Wproj, (float4*)wp,
                                    (KDIM * CDIM) / 4);

    // 1) qkv = x @ W_qkv + b     (M=200704, N=1152, K=384)
    gemm_tf32_kernel<<<dim3(N_QKV / 128, MROWS / 128), 128, GEMM_SMEM>>>(
        x, wq, bqkv, qkv, N_QKV);

    // 2) attention per (window, head)
    attn_kernel<<<dim3(BTOT, HEADS), 64>>>(qkv, relix, table, ctx);

    // 3) out = ctx @ W_proj + b  (M=200704, N=384, K=384)
    gemm_tf32_kernel<<<dim3(CDIM / 128, MROWS / 128), 128, GEMM_SMEM>>>(
        ctx, wp, bproj, out, CDIM);
}